// round 14
// baseline (speedup 1.0000x reference)
#include <cuda_runtime.h>
#include <cuda_bf16.h>
#include <cuda_fp16.h>
#include <cstdint>

#define B_ROWS  65536
#define DIM     256
#define HDIM    1024
#define MTILE   128
#define NCH     32             // N per chunk (24 via MMA, 8 via SIMT HFMA2)
#define NCHUNKS (HDIM / NCH)   // 32
#define NCTAS   (B_ROWS / MTILE) // 512

#define SKP     264
#define SKPB    (SKP * 2)              // 528 bytes
#define XB      (MTILE * SKPB)         // 67584  x-tile (fp16)
#define AB      (NCH * SKPB)           // 16896  one At chunk buffer
#define SMEM_BYTES (XB + 2 * AB)       // 101376 -> 2 CTAs/SM

__device__ __half g_At[HDIM * DIM];

__device__ __forceinline__ uint32_t smem_u32(const void* p) {
    uint32_t a;
    asm("{ .reg .u64 t; cvta.to.shared.u64 t, %1; cvt.u32.u64 %0, t; }"
        : "=r"(a) : "l"(p));
    return a;
}

#define LDSM4(r0, r1, r2, r3, addr) \
    asm volatile("ldmatrix.sync.aligned.m8n8.x4.shared.b16 {%0,%1,%2,%3}, [%4];" \
                 : "=r"(r0), "=r"(r1), "=r"(r2), "=r"(r3) : "r"(addr))

#define LDS128(r0, r1, r2, r3, addr) \
    asm volatile("ld.shared.v4.b32 {%0,%1,%2,%3}, [%4];" \
                 : "=r"(r0), "=r"(r1), "=r"(r2), "=r"(r3) : "r"(addr))

#define MMA16816H(c0, c1, a, b0, b1) \
    asm volatile("mma.sync.aligned.m16n8k16.row.col.f16.f16.f16.f16 " \
                 "{%0,%1}, {%2,%3,%4,%5}, {%6,%7}, {%0,%1};" \
                 : "+r"(c0), "+r"(c1) \
                 : "r"((a)[0]), "r"((a)[1]), "r"((a)[2]), "r"((a)[3]), "r"(b0), "r"(b1))

__device__ __forceinline__ float silu_f(float z) {
    float h = 0.5f * z;
    float t;
    asm("tanh.approx.f32 %0, %1;" : "=f"(t) : "f"(h));
    return fmaf(h, t, h);
}

__device__ __forceinline__ uint32_t pack_h2(float a, float b) {
    __half2 h = __floats2half2_rn(a, b);
    return *(uint32_t*)&h;
}

__device__ __forceinline__ float2 h2_to_f2(uint32_t u) {
    return __half22float2(*(__half2*)&u);
}

__device__ __forceinline__ __half2 u_as_h2(uint32_t u) { return *(__half2*)&u; }

__device__ __forceinline__ void stg_cs_zero16(float4* p) {
    asm volatile("st.global.cs.v4.f32 [%0], {%1,%1,%1,%1};"
                 :: "l"(p), "f"(0.0f) : "memory");
}

__global__ void cvt_A_kernel(const float* __restrict__ A) {
    __shared__ float tile[32][33];
    int n0 = blockIdx.x * 32;
    int k0 = blockIdx.y * 32;
    int tx = threadIdx.x, ty = threadIdx.y;
#pragma unroll
    for (int r = 0; r < 32; r += 8)
        tile[ty + r][tx] = A[(size_t)(k0 + ty + r) * HDIM + n0 + tx];
    __syncthreads();
#pragma unroll
    for (int r = 0; r < 32; r += 8)
        g_At[(size_t)(n0 + ty + r) * DIM + k0 + tx] = __float2half_rn(tile[tx][ty + r]);
}

__global__ __launch_bounds__(256, 2)
void gemm_silu_kernel(const float* __restrict__ x, float* __restrict__ out) {
    extern __shared__ char smem_raw[];
    __shared__ float red[128];
    __shared__ float rowacc[8][16];
    const uint32_t sxt = smem_u32(smem_raw);
    const uint32_t sab = sxt + XB;

    const int tid  = threadIdx.x;
    const int wid  = tid >> 5;
    const int lane = tid & 31;
    const int ct   = blockIdx.x;
    const size_t b0 = (size_t)ct * MTILE;

    // prefetch At chunk 0
    {
#pragma unroll
        for (int j = 0; j < 4; j++) {
            int idx = tid + j * 256;
            int nl  = idx >> 5;
            int kc  = idx & 31;
            uint32_t dst = sab + (uint32_t)nl * SKPB + (uint32_t)kc * 16;
            uint64_t src = __cvta_generic_to_global(g_At + (size_t)nl * DIM + kc * 8);
            asm volatile("cp.async.cg.shared.global [%0], [%1], 16;" :: "r"(dst), "l"(src));
        }
        asm volatile("cp.async.commit_group;" ::: "memory");
    }

    // stage x-tile as fp16 (SIMT path operand)
    {
        const float4* xg = (const float4*)(x + b0 * DIM);
#pragma unroll 4
        for (int t = 0; t < 32; t++) {
            int idx = tid + t * 256;
            int r = idx >> 6;
            int c4 = idx & 63;
            float4 v = xg[idx];
            uint32_t lo = pack_h2(v.x, v.y), hi = pack_h2(v.z, v.w);
            uint32_t addr = sxt + (uint32_t)r * SKPB + (uint32_t)c4 * 8;
            asm volatile("st.shared.v2.b32 [%0], {%1,%2};"
                         :: "r"(addr), "r"(lo), "r"(hi) : "memory");
        }
    }

    // A-fragments from global x, once
    uint32_t af[16][4];
    {
        int g = lane >> 2, q = lane & 3;
        const float* xr0 = x + (b0 + (size_t)(wid * 16 + g)) * DIM;
        const float* xr1 = xr0 + 8 * DIM;
#pragma unroll
        for (int kk = 0; kk < 16; kk++) {
            int k0 = kk * 16 + 2 * q;
            float2 v00 = *(const float2*)(xr0 + k0);
            float2 v10 = *(const float2*)(xr1 + k0);
            float2 v01 = *(const float2*)(xr0 + k0 + 8);
            float2 v11 = *(const float2*)(xr1 + k0 + 8);
            af[kk][0] = pack_h2(v00.x, v00.y);
            af[kk][1] = pack_h2(v10.x, v10.y);
            af[kk][2] = pack_h2(v01.x, v01.y);
            af[kk][3] = pack_h2(v11.x, v11.y);
        }
    }

    float rs0 = 0.f, rs1 = 0.f;
    float4* zball = (float4*)(out + (size_t)ct * 131072);

    const int col8 = lane & 7, rg = lane >> 3;
    const uint32_t xrb = sxt + (uint32_t)(wid * 16 + rg * 4) * SKPB;
    const int brow = lane & 7, bmat = lane >> 3;

    for (int c = 0; c < NCHUNKS; c++) {
        if (c + 1 < NCHUNKS) {
            uint32_t sa_n = sab + (uint32_t)((c + 1) & 1) * AB;
#pragma unroll
            for (int j = 0; j < 4; j++) {
                int idx = tid + j * 256;
                int nl  = idx >> 5;
                int kc  = idx & 31;
                uint32_t dst = sa_n + (uint32_t)nl * SKPB + (uint32_t)kc * 16;
                uint64_t src = __cvta_generic_to_global(
                    g_At + (size_t)((c + 1) * NCH + nl) * DIM + kc * 8);
                asm volatile("cp.async.cg.shared.global [%0], [%1], 16;" :: "r"(dst), "l"(src));
            }
            asm volatile("cp.async.commit_group;" ::: "memory");
        }

        {
            float4* zq = zball + (size_t)c * 1024;
#pragma unroll
            for (int j = 0; j < 4; j++) stg_cs_zero16(zq + tid + j * 256);
        }

        if (c + 1 < NCHUNKS) {
            asm volatile("cp.async.wait_group 1;" ::: "memory");
        } else {
            asm volatile("cp.async.wait_group 0;" ::: "memory");
        }
        __syncthreads();

        const uint32_t sa = sab + (uint32_t)(c & 1) * AB;
        const uint32_t bbase = sa + (uint32_t)brow * SKPB + (uint32_t)bmat * 16;
        const uint32_t bcol  = sa + (uint32_t)(24 + col8) * SKPB;

        __half2 acc[4];
        acc[0] = __float2half2_rn(0.f); acc[1] = acc[0];
        acc[2] = acc[0]; acc[3] = acc[0];
        uint32_t bbv[16];

#pragma unroll
        for (int nb = 0; nb < 3; nb++) {
            const uint32_t ba = bbase + (uint32_t)nb * 8u * SKPB;
            uint32_t bq[2][4];
            uint32_t d0 = 0u, d1 = 0u;
            LDSM4(bq[0][0], bq[0][1], bq[0][2], bq[0][3], ba);
#pragma unroll
            for (int j = 0; j < 8; j++) {
                const int cur = j & 1;
                const int step = nb * 8 + j;
                if (j < 7) {
                    LDSM4(bq[cur ^ 1][0], bq[cur ^ 1][1], bq[cur ^ 1][2], bq[cur ^ 1][3],
                          ba + (uint32_t)(j + 1) * 64);
                }
                MMA16816H(d0, d1, af[2 * j],     bq[cur][0], bq[cur][1]);
                MMA16816H(d0, d1, af[2 * j + 1], bq[cur][2], bq[cur][3]);

                const int u_lo = (step * 128) / 24;
                const int u_hi = ((step + 1) * 128) / 24;
#pragma unroll
                for (int u = u_lo; u < u_hi; u++) {
                    const int kb = u >> 4;
                    const int r  = (u >> 2) & 3;
                    const int s  = u & 3;
                    if ((u & 15) == 0) {
                        LDS128(bbv[0],  bbv[1],  bbv[2],  bbv[3],  bcol + (uint32_t)kb * 64);
                        LDS128(bbv[4],  bbv[5],  bbv[6],  bbv[7],  bcol + (uint32_t)kb * 64 + 16);
                        LDS128(bbv[8],  bbv[9],  bbv[10], bbv[11], bcol + (uint32_t)kb * 64 + 32);
                        LDS128(bbv[12], bbv[13], bbv[14], bbv[15], bcol + (uint32_t)kb * 64 + 48);
                    }
                    uint32_t x0, x1, x2, x3;
                    LDS128(x0, x1, x2, x3,
                           xrb + (uint32_t)r * SKPB + (uint32_t)kb * 64 + (uint32_t)s * 16);
                    acc[r] = __hfma2(u_as_h2(x0), u_as_h2(bbv[s * 4 + 0]), acc[r]);
                    acc[r] = __hfma2(u_as_h2(x1), u_as_h2(bbv[s * 4 + 1]), acc[r]);
                    acc[r] = __hfma2(u_as_h2(x2), u_as_h2(bbv[s * 4 + 2]), acc[r]);
                    acc[r] = __hfma2(u_as_h2(x3), u_as_h2(bbv[s * 4 + 3]), acc[r]);
                }
            }
            float2 a0 = h2_to_f2(d0);
            float2 a1 = h2_to_f2(d1);
            rs0 += silu_f(a0.x) + silu_f(a0.y);
            rs1 += silu_f(a1.x) + silu_f(a1.y);
        }

        // SIMT fold: silu per (row,col) z FIRST, then reduce over the 8 col-lanes
#pragma unroll
        for (int r = 0; r < 4; r++) {
            float2 vf = __half22float2(acc[r]);
            float v = silu_f(vf.x + vf.y);
            v += __shfl_xor_sync(0xFFFFFFFFu, v, 1);
            v += __shfl_xor_sync(0xFFFFFFFFu, v, 2);
            v += __shfl_xor_sync(0xFFFFFFFFu, v, 4);
            if (col8 == 0) rowacc[wid][rg * 4 + r] = v;
        }
        __syncwarp();
        if ((lane & 3) == 0) {
            int g = lane >> 2;
            rs0 += rowacc[wid][g];
            rs1 += rowacc[wid][8 + g];
        }
        __syncwarp();
        __syncthreads();
    }

    rs0 += __shfl_xor_sync(0xFFFFFFFFu, rs0, 1);
    rs0 += __shfl_xor_sync(0xFFFFFFFFu, rs0, 2);
    rs1 += __shfl_xor_sync(0xFFFFFFFFu, rs1, 1);
    rs1 += __shfl_xor_sync(0xFFFFFFFFu, rs1, 2);
    if ((lane & 3) == 0) {
        int gid = lane >> 2;
        red[wid * 16 + gid]     = rs0;
        red[wid * 16 + gid + 8] = rs1;
    }
    __syncthreads();

    if (tid < 128) {
        float s = red[tid];
        size_t b = b0 + (size_t)tid;
        size_t g = b >> 6;
        int i2 = (int)(b & 63) * 2;
        float* og = out + g * 65536;
        og[(size_t)i2 * 256 + 128 + i2]       =  s;
        og[(size_t)(i2 + 1) * 256 + 129 + i2] =  s;
        og[(size_t)(128 + i2) * 256 + i2]     = -s;
        og[(size_t)(129 + i2) * 256 + i2 + 1] = -s;
    }
}

extern "C" void kernel_launch(void* const* d_in, const int* in_sizes, int n_in,
                              void* d_out, int out_size) {
    const float* x = (const float*)d_in[0];
    const float* A = (const float*)d_in[1];
    float* out = (float*)d_out;

    cudaFuncSetAttribute(gemm_silu_kernel,
                         cudaFuncAttributeMaxDynamicSharedMemorySize, SMEM_BYTES);

    cvt_A_kernel<<<dim3(32, 8), dim3(32, 8)>>>(A);
    gemm_silu_kernel<<<NCTAS, 256, SMEM_BYTES>>>(x, out);
}

// round 17
// speedup vs baseline: 1.9679x; 1.9679x over previous
#include <cuda_runtime.h>
#include <cuda_bf16.h>
#include <cuda_fp16.h>
#include <cstdint>

// Problem constants (fixed by setup_inputs):
//   x: [65536, 256] f32,  A: [256, 1024] f32
//   out: [1024, 256, 256] f32  (G=1024 blocks of 256x256)
#define B_ROWS  65536
#define DIM     256
#define HDIM    1024
#define MTILE   128
#define NCH     64             // N per chunk
#define NCHUNKS (HDIM / NCH)   // 16
#define NCTAS   (B_ROWS / MTILE) // 512

#define SKP     264                    // fp16 elems per padded SMEM row (528 B; odd 16B stride -> conflict-free)
#define SKPB    (SKP * 2)              // 528 bytes
#define ABYTES  (NCH * SKPB)           // 33792
#define SMEM_BYTES (2 * ABYTES)        // 67584  -> 3 CTAs/SM (203KB SMEM, 85 regs)

// Device scratch: A^T in fp16, [N=1024][K=256] row-major
__device__ __half g_At[HDIM * DIM];

// ---------------- helpers ----------------
__device__ __forceinline__ uint32_t smem_u32(const void* p) {
    uint32_t a;
    asm("{ .reg .u64 t; cvta.to.shared.u64 t, %1; cvt.u32.u64 %0, t; }"
        : "=r"(a) : "l"(p));
    return a;
}

#define LDSM4(r0, r1, r2, r3, addr) \
    asm volatile("ldmatrix.sync.aligned.m8n8.x4.shared.b16 {%0,%1,%2,%3}, [%4];" \
                 : "=r"(r0), "=r"(r1), "=r"(r2), "=r"(r3) : "r"(addr))

// fp16 in / fp16 accumulate: D,C = {2 x b32} (4 halves)
#define MMA16816H(c0, c1, a, b0, b1) \
    asm volatile("mma.sync.aligned.m16n8k16.row.col.f16.f16.f16.f16 " \
                 "{%0,%1}, {%2,%3,%4,%5}, {%6,%7}, {%0,%1};" \
                 : "+r"(c0), "+r"(c1) \
                 : "r"((a)[0]), "r"((a)[1]), "r"((a)[2]), "r"((a)[3]), "r"(b0), "r"(b1))

__device__ __forceinline__ float silu_f(float z) {
    float h = 0.5f * z;
    float t;
    asm("tanh.approx.f32 %0, %1;" : "=f"(t) : "f"(h));
    return fmaf(h, t, h);      // 0.5z + 0.5z*tanh(z/2) = silu(z)
}

__device__ __forceinline__ uint32_t pack_h2(float a, float b) {
    __half2 h = __floats2half2_rn(a, b);
    return *(uint32_t*)&h;
}

__device__ __forceinline__ float2 h2_to_f2(uint32_t u) {
    return __half22float2(*(__half2*)&u);
}

// streaming (evict-first) 16B zero store
__device__ __forceinline__ void stg_cs_zero16(float4* p) {
    asm volatile("st.global.cs.v4.f32 [%0], {%1,%1,%1,%1};"
                 :: "l"(p), "f"(0.0f) : "memory");
}

// ---------------- A transpose+convert: A[k][n] f32 -> g_At[n][k] fp16 ----------------
__global__ void cvt_A_kernel(const float* __restrict__ A) {
    __shared__ float tile[32][33];
    int n0 = blockIdx.x * 32;
    int k0 = blockIdx.y * 32;
    int tx = threadIdx.x, ty = threadIdx.y;   // block (32, 8)
#pragma unroll
    for (int r = 0; r < 32; r += 8)
        tile[ty + r][tx] = A[(size_t)(k0 + ty + r) * HDIM + n0 + tx];
    __syncthreads();
#pragma unroll
    for (int r = 0; r < 32; r += 8)
        g_At[(size_t)(n0 + ty + r) * DIM + k0 + tx] = __float2half_rn(tile[tx][ty + r]);
}

// ---------------- fused GEMM(fp16 HMMA) + silu-rowsum + zero-fill + scatter ----------------
__global__ __launch_bounds__(256, 3)
void gemm_silu_kernel(const float* __restrict__ x, float* __restrict__ out) {
    extern __shared__ char smem_raw[];
    __shared__ float red[128];
    const uint32_t sa0 = smem_u32(smem_raw);

    const int tid  = threadIdx.x;
    const int wid  = tid >> 5;        // 8 warps; warp w owns m-rows [16w, 16w+16)
    const int lane = tid & 31;
    const int ct   = blockIdx.x;
    const size_t b0 = (size_t)ct * MTILE;

    // ---- 1) prefetch At chunk 0 via cp.async ----
    {
#pragma unroll
        for (int j = 0; j < 8; j++) {
            int idx = tid + j * 256;          // 2048 x 16B
            int nl  = idx >> 5;               // 32 16B-chunks per row
            int kc  = idx & 31;
            uint32_t dst = sa0 + (uint32_t)nl * SKPB + (uint32_t)kc * 16;
            uint64_t src = __cvta_generic_to_global(g_At + (size_t)nl * DIM + kc * 8);
            asm volatile("cp.async.cg.shared.global [%0], [%1], 16;" :: "r"(dst), "l"(src));
        }
        asm volatile("cp.async.commit_group;" ::: "memory");
    }

    // ---- 2) load A-fragments for all K directly from global x (f32 -> fp16 packs), ONCE ----
    uint32_t af[16][4];
    {
        int g = lane >> 2, q = lane & 3;
        const float* xr0 = x + (b0 + (size_t)(wid * 16 + g)) * DIM;   // m_lo row
        const float* xr1 = xr0 + 8 * DIM;                             // m_hi row
#pragma unroll
        for (int kk = 0; kk < 16; kk++) {
            int k0 = kk * 16 + 2 * q;
            float2 v00 = *(const float2*)(xr0 + k0);
            float2 v10 = *(const float2*)(xr1 + k0);
            float2 v01 = *(const float2*)(xr0 + k0 + 8);
            float2 v11 = *(const float2*)(xr1 + k0 + 8);
            af[kk][0] = pack_h2(v00.x, v00.y);
            af[kk][1] = pack_h2(v10.x, v10.y);
            af[kk][2] = pack_h2(v01.x, v01.y);
            af[kk][3] = pack_h2(v11.x, v11.y);
        }
    }

    float rs0 = 0.f, rs1 = 0.f;   // row sums for m = 16w+g and 16w+g+8
    float4* zball = (float4*)(out + (size_t)ct * 131072);  // this CTA's 512KB region

    // ---- 3) n-chunk loop: cp.async double-buffered At, interleaved zero-fill, MMA + silu ----
    const int brow = lane & 7, bmat = lane >> 3;
    for (int c = 0; c < NCHUNKS; c++) {
        if (c + 1 < NCHUNKS) {
            uint32_t sa_n = sa0 + (uint32_t)((c + 1) & 1) * ABYTES;
#pragma unroll
            for (int j = 0; j < 8; j++) {
                int idx = tid + j * 256;
                int nl  = idx >> 5;
                int kc  = idx & 31;
                uint32_t dst = sa_n + (uint32_t)nl * SKPB + (uint32_t)kc * 16;
                uint64_t src = __cvta_generic_to_global(
                    g_At + (size_t)((c + 1) * NCH + nl) * DIM + kc * 8);
                asm volatile("cp.async.cg.shared.global [%0], [%1], 16;" :: "r"(dst), "l"(src));
            }
            asm volatile("cp.async.commit_group;" ::: "memory");
        }

        // interleaved zero-fill: 1/16 of this CTA's output region (32KB, streaming stores)
        {
            float4* zq = zball + (size_t)c * 2048;
#pragma unroll
            for (int j = 0; j < 8; j++) stg_cs_zero16(zq + tid + j * 256);
        }

        if (c + 1 < NCHUNKS) {
            asm volatile("cp.async.wait_group 1;" ::: "memory");
        } else {
            asm volatile("cp.async.wait_group 0;" ::: "memory");
        }
        __syncthreads();

        const uint32_t sa = sa0 + (uint32_t)(c & 1) * ABYTES;
        const uint32_t bbase = sa + (uint32_t)brow * SKPB + (uint32_t)bmat * 16;

#pragma unroll
        for (int nb = 0; nb < 8; nb++) {
            const uint32_t ba = bbase + (uint32_t)nb * 8 * SKPB;
            uint32_t cA0 = 0u, cA1 = 0u;   // even-kb chain (f16x2 accum)
            uint32_t cB0 = 0u, cB1 = 0u;   // odd-kb chain
            uint32_t bp[2][4];             // double-buffered B frags
            LDSM4(bp[0][0], bp[0][1], bp[0][2], bp[0][3], ba);
#pragma unroll
            for (int kb = 0; kb < 8; kb++) {
                const int cur = kb & 1;
                if (kb < 7) {
                    LDSM4(bp[cur ^ 1][0], bp[cur ^ 1][1], bp[cur ^ 1][2], bp[cur ^ 1][3],
                          ba + (uint32_t)(kb + 1) * 64);
                }
                MMA16816H(cA0, cA1, af[2 * kb],     bp[cur][0], bp[cur][1]);
                MMA16816H(cB0, cB1, af[2 * kb + 1], bp[cur][2], bp[cur][3]);
            }
            // combine chains in f32, apply silu, fold into rowsums
            float2 a0 = h2_to_f2(cA0), b0f = h2_to_f2(cB0);   // row g:   cols 2q, 2q+1
            float2 a1 = h2_to_f2(cA1), b1f = h2_to_f2(cB1);   // row g+8
            rs0 += silu_f(a0.x + b0f.x) + silu_f(a0.y + b0f.y);
            rs1 += silu_f(a1.x + b1f.x) + silu_f(a1.y + b1f.y);
        }
        __syncthreads();   // buffer (c&1) may be overwritten by next iteration's prefetch
    }

    // ---- 4) reduce across the 4 threads of each mma group, stage to shared ----
    rs0 += __shfl_xor_sync(0xFFFFFFFFu, rs0, 1);
    rs0 += __shfl_xor_sync(0xFFFFFFFFu, rs0, 2);
    rs1 += __shfl_xor_sync(0xFFFFFFFFu, rs1, 1);
    rs1 += __shfl_xor_sync(0xFFFFFFFFu, rs1, 2);
    if ((lane & 3) == 0) {
        int gid = lane >> 2;
        red[wid * 16 + gid]     = rs0;
        red[wid * 16 + gid + 8] = rs1;
    }
    __syncthreads();

    // ---- 5) scatter +/- s onto the block anti-diagonals (region already zeroed by this CTA) ----
    if (tid < 128) {
        float s = red[tid];
        size_t b = b0 + (size_t)tid;
        size_t g = b >> 6;                 // G block (64 rows per block)
        int i2 = (int)(b & 63) * 2;
        float* og = out + g * 65536;
        og[(size_t)i2 * 256 + 128 + i2]       =  s;   // top-right diag, even
        og[(size_t)(i2 + 1) * 256 + 129 + i2] =  s;   // top-right diag, odd
        og[(size_t)(128 + i2) * 256 + i2]     = -s;   // bottom-left diag, even
        og[(size_t)(129 + i2) * 256 + i2 + 1] = -s;   // bottom-left diag, odd
    }
}

// ---------------- launch ----------------
extern "C" void kernel_launch(void* const* d_in, const int* in_sizes, int n_in,
                              void* d_out, int out_size) {
    const float* x = (const float*)d_in[0];   // [65536, 256]
    const float* A = (const float*)d_in[1];   // [256, 1024]
    float* out = (float*)d_out;               // [1024, 256, 256]

    cudaFuncSetAttribute(gemm_silu_kernel,
                         cudaFuncAttributeMaxDynamicSharedMemorySize, SMEM_BYTES);

    cvt_A_kernel<<<dim3(32, 8), dim3(32, 8)>>>(A);
    gemm_silu_kernel<<<NCTAS, 256, SMEM_BYTES>>>(x, out);
}